// round 1
// baseline (speedup 1.0000x reference)
#include <cuda_runtime.h>
#include <math.h>

// Problem dims
#define B_   128
#define P_   196
#define E_   2048
#define A_   512
#define M_   (B_ * P_)   // 25088

// Scratch (allocation-free rule: __device__ globals)
__device__ float g_att1[(size_t)M_ * A_];   // [25088, 512]  ~51.4 MB
__device__ float g_att2[B_ * A_];           // [128, 512]

// ---------------------------------------------------------------------------
// Kernel 1: att2[b,a] = decoder_hidden[b,:] @ W_dec[:,a] + b_dec[a]
// grid=(128), block=(512)
// ---------------------------------------------------------------------------
__global__ void att2_kernel(const float* __restrict__ dh,
                            const float* __restrict__ Wd,
                            const float* __restrict__ bd,
                            float* __restrict__ att2) {
    __shared__ float h[A_];
    const int b = blockIdx.x;
    const int a = threadIdx.x;
    h[a] = dh[b * A_ + a];
    __syncthreads();
    float acc = bd[a];
#pragma unroll 8
    for (int d = 0; d < A_; d++)
        acc += h[d] * Wd[(size_t)d * A_ + a];
    att2[b * A_ + a] = acc;
}

// ---------------------------------------------------------------------------
// Kernel 2: att1 = enc[M,E] @ W_enc[E,A] + b_enc   (fp32 SGEMM, 128x128x16)
// grid=(A_/128, M_/128) = (4,196), block=256, 8x8 microtile per thread
// ---------------------------------------------------------------------------
#define BM 128
#define BN 128
#define BK 16

__global__ __launch_bounds__(256, 2)
void gemm_att1(const float* __restrict__ A,
               const float* __restrict__ W,
               const float* __restrict__ bias,
               float* __restrict__ C) {
    __shared__ float As[BK][BM];   // transposed A tile: As[k][m]
    __shared__ float Bs[BK][BN];

    const int m0  = blockIdx.y * BM;
    const int n0  = blockIdx.x * BN;
    const int tid = threadIdx.x;
    const int tx  = tid & 15;     // 0..15 -> columns
    const int ty  = tid >> 4;     // 0..15 -> rows

    float acc[8][8];
#pragma unroll
    for (int i = 0; i < 8; i++)
#pragma unroll
        for (int j = 0; j < 8; j++) acc[i][j] = 0.f;

    const float* Aptr = A + (size_t)m0 * E_;
    const float* Wptr = W + n0;

    for (int k0 = 0; k0 < E_; k0 += BK) {
        // Load A tile: 128 rows x 16 k  (512 float4, 2 per thread)
#pragma unroll
        for (int i = 0; i < 2; i++) {
            int f  = tid + i * 256;
            int r  = f >> 2;
            int c4 = (f & 3) * 4;
            float4 v = *reinterpret_cast<const float4*>(
                Aptr + (size_t)r * E_ + k0 + c4);
            As[c4 + 0][r] = v.x;
            As[c4 + 1][r] = v.y;
            As[c4 + 2][r] = v.z;
            As[c4 + 3][r] = v.w;
        }
        // Load W tile: 16 k x 128 n  (512 float4, 2 per thread)
#pragma unroll
        for (int i = 0; i < 2; i++) {
            int f  = tid + i * 256;
            int kr = f >> 5;
            int c4 = (f & 31) * 4;
            *reinterpret_cast<float4*>(&Bs[kr][c4]) =
                *reinterpret_cast<const float4*>(
                    Wptr + (size_t)(k0 + kr) * A_ + c4);
        }
        __syncthreads();

#pragma unroll
        for (int k = 0; k < BK; k++) {
            float ra[8], rb[8];
            *reinterpret_cast<float4*>(ra)     = *reinterpret_cast<const float4*>(&As[k][ty * 4]);
            *reinterpret_cast<float4*>(ra + 4) = *reinterpret_cast<const float4*>(&As[k][64 + ty * 4]);
            *reinterpret_cast<float4*>(rb)     = *reinterpret_cast<const float4*>(&Bs[k][tx * 4]);
            *reinterpret_cast<float4*>(rb + 4) = *reinterpret_cast<const float4*>(&Bs[k][64 + tx * 4]);
#pragma unroll
            for (int i = 0; i < 8; i++)
#pragma unroll
                for (int j = 0; j < 8; j++)
                    acc[i][j] = fmaf(ra[i], rb[j], acc[i][j]);
        }
        __syncthreads();
    }

    // Epilogue: + b_enc, store
#pragma unroll
    for (int i = 0; i < 8; i++) {
        int row = m0 + ((i < 4) ? (ty * 4 + i) : (64 + ty * 4 + i - 4));
#pragma unroll
        for (int jh = 0; jh < 2; jh++) {
            int col = n0 + ((jh == 0) ? (tx * 4) : (64 + tx * 4));
            float4 v;
            v.x = acc[i][jh * 4 + 0] + bias[col + 0];
            v.y = acc[i][jh * 4 + 1] + bias[col + 1];
            v.z = acc[i][jh * 4 + 2] + bias[col + 2];
            v.w = acc[i][jh * 4 + 3] + bias[col + 3];
            *reinterpret_cast<float4*>(C + (size_t)row * A_ + col) = v;
        }
    }
}

// ---------------------------------------------------------------------------
// Kernel 3: per-batch scores + softmax over P
//   att[p] = relu(att1[b,p,:] + att2[b,:]) . W_full + b_full
//   alpha  = softmax(att)  -> written into d_out's alpha region
// grid=(128), block=(256)
// ---------------------------------------------------------------------------
__global__ void score_softmax_kernel(const float* __restrict__ att1,
                                     const float* __restrict__ att2,
                                     const float* __restrict__ Wf,
                                     const float* __restrict__ bf,
                                     float* __restrict__ alpha_out) {
    __shared__ float a2[A_];
    __shared__ float wf[A_];
    __shared__ float sc[P_ + 4];
    __shared__ float red[256];

    const int b   = blockIdx.x;
    const int tid = threadIdx.x;

    a2[tid]       = att2[b * A_ + tid];
    a2[tid + 256] = att2[b * A_ + tid + 256];
    wf[tid]       = Wf[tid];
    wf[tid + 256] = Wf[tid + 256];
    __syncthreads();

    const int w    = tid >> 5;
    const int lane = tid & 31;
    const float bfull = *bf;

    for (int p = w; p < P_; p += 8) {
        const float* row = att1 + ((size_t)b * P_ + p) * A_;
        float s = 0.f;
#pragma unroll 4
        for (int a = lane; a < A_; a += 32) {
            float v = row[a] + a2[a];
            s += fmaxf(v, 0.f) * wf[a];
        }
#pragma unroll
        for (int o = 16; o; o >>= 1)
            s += __shfl_xor_sync(0xffffffffu, s, o);
        if (lane == 0) sc[p] = s + bfull;
    }
    __syncthreads();

    // softmax over 196
    float v = (tid < P_) ? sc[tid] : -INFINITY;
    red[tid] = v;
    __syncthreads();
#pragma unroll
    for (int s = 128; s; s >>= 1) {
        if (tid < s) red[tid] = fmaxf(red[tid], red[tid + s]);
        __syncthreads();
    }
    const float mx = red[0];
    __syncthreads();
    float e = (tid < P_) ? expf(v - mx) : 0.f;
    red[tid] = e;
    __syncthreads();
#pragma unroll
    for (int s = 128; s; s >>= 1) {
        if (tid < s) red[tid] += red[tid + s];
        __syncthreads();
    }
    const float inv = 1.f / red[0];
    if (tid < P_) alpha_out[b * P_ + tid] = e * inv;
}

// ---------------------------------------------------------------------------
// Kernel 4: awe[b,e] = sum_p enc[b,p,e] * alpha[b,p]
// grid=(E_/256, B_), block=(256)
// ---------------------------------------------------------------------------
__global__ void weighted_kernel(const float* __restrict__ enc,
                                const float* __restrict__ alpha,
                                float* __restrict__ out) {
    __shared__ float al[P_];
    const int b = blockIdx.y;
    const int e = blockIdx.x * 256 + threadIdx.x;
    if (threadIdx.x < P_) al[threadIdx.x] = alpha[b * P_ + threadIdx.x];
    __syncthreads();

    const float* base = enc + (size_t)b * P_ * E_ + e;
    float acc = 0.f;
#pragma unroll 4
    for (int p = 0; p < P_; p++)
        acc = fmaf(base[(size_t)p * E_], al[p], acc);
    out[b * E_ + e] = acc;
}

// ---------------------------------------------------------------------------
// Launch
// Inputs (metadata order): encoder_out, decoder_hidden, W_enc, b_enc,
//                          W_dec, b_dec, W_full, b_full
// Output: [awe (128*2048 floats)] [alpha (128*196 floats)]
// ---------------------------------------------------------------------------
extern "C" void kernel_launch(void* const* d_in, const int* in_sizes, int n_in,
                              void* d_out, int out_size) {
    const float* enc   = (const float*)d_in[0];
    const float* dh    = (const float*)d_in[1];
    const float* W_enc = (const float*)d_in[2];
    const float* b_enc = (const float*)d_in[3];
    const float* W_dec = (const float*)d_in[4];
    const float* b_dec = (const float*)d_in[5];
    const float* W_ful = (const float*)d_in[6];
    const float* b_ful = (const float*)d_in[7];

    float* out   = (float*)d_out;
    float* awe   = out;                    // [128, 2048]
    float* alpha = out + (size_t)B_ * E_;  // [128, 196]

    float* att1;
    float* att2;
    cudaGetSymbolAddress((void**)&att1, g_att1);
    cudaGetSymbolAddress((void**)&att2, g_att2);

    // 1. att2 = dh @ W_dec + b_dec
    att2_kernel<<<B_, A_>>>(dh, W_dec, b_dec, att2);

    // 2. att1 = enc @ W_enc + b_enc
    dim3 gg(A_ / BN, M_ / BM);   // (4, 196)
    gemm_att1<<<gg, 256>>>(enc, W_enc, b_enc, att1);

    // 3. scores + softmax -> alpha
    score_softmax_kernel<<<B_, 256>>>(att1, att2, W_ful, b_ful, alpha);

    // 4. weighted encoding
    dim3 gw(E_ / 256, B_);
    weighted_kernel<<<gw, 256>>>(enc, alpha, awe);
}

// round 3
// speedup vs baseline: 2.1943x; 2.1943x over previous
#include <cuda_runtime.h>
#include <cuda_bf16.h>
#include <math.h>
#include <stdint.h>

#define B_   128
#define P_   196
#define E_   2048
#define A_   512
#define M_   (B_ * P_)   // 25088

// ---------------- scratch (__device__ globals; no allocs) ----------------
__device__ __align__(16) __nv_bfloat16 g_AHi[(size_t)M_ * E_];   // enc hi  ~102.8MB
__device__ __align__(16) __nv_bfloat16 g_ALo[(size_t)M_ * E_];   // enc lo
__device__ __align__(16) __nv_bfloat16 g_WHi[(size_t)E_ * A_];   // W_enc hi [E,A]
__device__ __align__(16) __nv_bfloat16 g_WLo[(size_t)E_ * A_];
__device__ float g_att2[B_ * A_];
__device__ float g_part[4 * M_];       // per-(n-block) partial scores

// ---------------- small helpers ----------------
__device__ __forceinline__ uint32_t smem_u32(const void* p) {
    uint32_t a;
    asm("{ .reg .u64 t; cvta.to.shared.u64 t, %1; cvt.u32.u64 %0, t; }"
        : "=r"(a) : "l"(p));
    return a;
}
__device__ __forceinline__ void cp16(uint32_t dst, const void* src) {
    asm volatile("cp.async.cg.shared.global [%0], [%1], 16;"
                 :: "r"(dst), "l"(src) : "memory");
}
__device__ __forceinline__ void cp_commit() {
    asm volatile("cp.async.commit_group;" ::: "memory");
}
__device__ __forceinline__ void cp_wait1() {
    asm volatile("cp.async.wait_group 1;" ::: "memory");
}
__device__ __forceinline__ void ldsm_x4(uint32_t* r, uint32_t addr) {
    asm volatile("ldmatrix.sync.aligned.m8n8.x4.shared.b16 {%0,%1,%2,%3}, [%4];"
                 : "=r"(r[0]), "=r"(r[1]), "=r"(r[2]), "=r"(r[3]) : "r"(addr));
}
__device__ __forceinline__ void ldsm_x4_t(uint32_t* r, uint32_t addr) {
    asm volatile("ldmatrix.sync.aligned.m8n8.x4.trans.shared.b16 {%0,%1,%2,%3}, [%4];"
                 : "=r"(r[0]), "=r"(r[1]), "=r"(r[2]), "=r"(r[3]) : "r"(addr));
}
__device__ __forceinline__ void mma_bf16(float* c, const uint32_t* a,
                                         uint32_t b0, uint32_t b1) {
    asm volatile(
        "mma.sync.aligned.m16n8k16.row.col.f32.bf16.bf16.f32 "
        "{%0,%1,%2,%3}, {%4,%5,%6,%7}, {%8,%9}, {%0,%1,%2,%3};"
        : "+f"(c[0]), "+f"(c[1]), "+f"(c[2]), "+f"(c[3])
        : "r"(a[0]), "r"(a[1]), "r"(a[2]), "r"(a[3]), "r"(b0), "r"(b1));
}
__device__ __forceinline__ uint32_t pack_bf2(__nv_bfloat16 x, __nv_bfloat16 y) {
    __nv_bfloat162 t = __halves2bfloat162(x, y);   // x -> low 16 bits
    return *reinterpret_cast<uint32_t*>(&t);
}

// ---------------------------------------------------------------------------
// Kernel A: fp32 -> bf16 hi/lo split (elementwise, float4 granularity)
// ---------------------------------------------------------------------------
__global__ void split_kernel(const float* __restrict__ in,
                             __nv_bfloat16* __restrict__ hi,
                             __nv_bfloat16* __restrict__ lo, int n4) {
    int i = blockIdx.x * 256 + threadIdx.x;
    if (i >= n4) return;
    float4 v = reinterpret_cast<const float4*>(in)[i];
    __nv_bfloat16 h0 = __float2bfloat16_rn(v.x);
    __nv_bfloat16 h1 = __float2bfloat16_rn(v.y);
    __nv_bfloat16 h2 = __float2bfloat16_rn(v.z);
    __nv_bfloat16 h3 = __float2bfloat16_rn(v.w);
    __nv_bfloat16 l0 = __float2bfloat16_rn(v.x - __bfloat162float(h0));
    __nv_bfloat16 l1 = __float2bfloat16_rn(v.y - __bfloat162float(h1));
    __nv_bfloat16 l2 = __float2bfloat16_rn(v.z - __bfloat162float(h2));
    __nv_bfloat16 l3 = __float2bfloat16_rn(v.w - __bfloat162float(h3));
    reinterpret_cast<uint2*>(hi)[i] = make_uint2(pack_bf2(h0, h1), pack_bf2(h2, h3));
    reinterpret_cast<uint2*>(lo)[i] = make_uint2(pack_bf2(l0, l1), pack_bf2(l2, l3));
}

// ---------------------------------------------------------------------------
// Kernel B: att2 = decoder_hidden @ W_dec + b_dec   (tiny, fp32)
// ---------------------------------------------------------------------------
__global__ void att2_kernel(const float* __restrict__ dh,
                            const float* __restrict__ Wd,
                            const float* __restrict__ bd,
                            float* __restrict__ att2) {
    __shared__ float h[A_];
    const int b = blockIdx.x;
    const int a = threadIdx.x;
    h[a] = dh[b * A_ + a];
    __syncthreads();
    float acc = bd[a];
#pragma unroll 8
    for (int d = 0; d < A_; d++)
        acc += h[d] * Wd[(size_t)d * A_ + a];
    att2[b * A_ + a] = acc;
}

// ---------------------------------------------------------------------------
// Kernel C: bf16x3 mma.sync GEMM with fused score epilogue.
// C_tile[128x128] = enc[128xE] @ W[Ex128] via (aH bH + aH bL + aL bH).
// score partial = sum_cols relu(C + b_enc + att2) * W_full  -> g_part[bx][m]
// grid=(4,196), block=256 (8 warps, 2Mx4N, warp tile 64x32)
// ---------------------------------------------------------------------------
#define BK         32
#define NKCH       (E_ / BK)        // 64
#define AS_HI      0
#define AS_LO      10240            // 128 rows * 80B
#define BS_HI      20480
#define BS_LO      29184            // 32 rows * 272B
#define STAGE      37888
#define EPI_OFF    (2 * STAGE)      // 75776
#define SMEM_TOT   (EPI_OFF + 3 * 128 * 4)   // 77312

__global__ __launch_bounds__(256)
void gemm_score_kernel(const __nv_bfloat16* __restrict__ AHi,
                       const __nv_bfloat16* __restrict__ ALo,
                       const __nv_bfloat16* __restrict__ WHi,
                       const __nv_bfloat16* __restrict__ WLo,
                       const float* __restrict__ bEnc,
                       const float* __restrict__ att2,
                       const float* __restrict__ Wf,
                       float* __restrict__ part) {
    extern __shared__ char smem[];
    const uint32_t sb = smem_u32(smem);
    const int tid  = threadIdx.x;
    const int lane = tid & 31;
    const int wid  = tid >> 5;
    const int warpM = wid >> 2;          // 0..1
    const int warpN = wid & 3;           // 0..3
    const int m0 = blockIdx.y * 128;
    const int n0 = blockIdx.x * 128;

    float* sum0 = (float*)(smem + EPI_OFF);
    float* sum1 = sum0 + 128;
    float* swf  = sum1 + 128;
    const int b0 = m0 / P_;
    const int rowsplit = (b0 + 1) * P_ - m0;   // rows >= this use batch b0+1
    if (tid < 128) {
        const int b1 = (b0 + 1 < B_) ? b0 + 1 : B_ - 1;
        float be = bEnc[n0 + tid];
        sum0[tid] = be + att2[b0 * A_ + n0 + tid];
        sum1[tid] = be + att2[b1 * A_ + n0 + tid];
        swf[tid]  = Wf[n0 + tid];
    }

    float acc[4][4][4];
#pragma unroll
    for (int i = 0; i < 4; i++)
#pragma unroll
        for (int j = 0; j < 4; j++)
#pragma unroll
            for (int q = 0; q < 4; q++) acc[i][j][q] = 0.f;

    // ---- stage loader (all cp.async) ----
    auto load_stage = [&](int st, int k0) {
        const uint32_t sbase = sb + st * STAGE;
#pragma unroll
        for (int i = 0; i < 2; i++) {
            int idx = tid + i * 256;               // 0..511
            int r = idx >> 2, q = idx & 3;         // A: 128 rows x 4 chunks
            size_t go = (size_t)(m0 + r) * E_ + k0 + q * 8;
            uint32_t so = (uint32_t)(r * 80 + q * 16);
            cp16(sbase + AS_HI + so, AHi + go);
            cp16(sbase + AS_LO + so, ALo + go);
        }
#pragma unroll
        for (int i = 0; i < 2; i++) {
            int idx = tid + i * 256;               // 0..511
            int k = idx >> 4, q = idx & 15;        // B: 32 rows x 16 chunks
            size_t go = (size_t)(k0 + k) * A_ + n0 + q * 8;
            uint32_t so = (uint32_t)(k * 272 + q * 16);
            cp16(sbase + BS_HI + so, WHi + go);
            cp16(sbase + BS_LO + so, WLo + go);
        }
    };

    load_stage(0, 0);
    cp_commit();

    // precomputed ldmatrix lane addressing
    const uint32_t a_row  = (uint32_t)(warpM * 64 + (lane & 15));
    const uint32_t a_colb = (uint32_t)((lane >> 4) * 16);
    const uint32_t b_krow = (uint32_t)(((lane >> 3) & 1) * 8 + (lane & 7));
    const uint32_t b_colb = (uint32_t)((warpN * 32 + (lane >> 4) * 8) * 2);

    for (int c = 0; c < NKCH; ++c) {
        if (c + 1 < NKCH) load_stage((c + 1) & 1, (c + 1) * BK);
        cp_commit();
        cp_wait1();
        __syncthreads();

        const uint32_t sbase = sb + (c & 1) * STAGE;
#pragma unroll
        for (int kk = 0; kk < 32; kk += 16) {
            uint32_t aH[4][4], aL[4][4], bH[2][4], bL[2][4];
#pragma unroll
            for (int mf = 0; mf < 4; mf++) {
                uint32_t ad = sbase + (a_row + mf * 16) * 80 + kk * 2 + a_colb;
                ldsm_x4(aH[mf], ad + AS_HI);
                ldsm_x4(aL[mf], ad + AS_LO);
            }
#pragma unroll
            for (int np = 0; np < 2; np++) {
                uint32_t bd = sbase + (b_krow + kk) * 272 + b_colb + np * 32;
                ldsm_x4_t(bH[np], bd + BS_HI);
                ldsm_x4_t(bL[np], bd + BS_LO);
            }
#pragma unroll
            for (int mf = 0; mf < 4; mf++)
#pragma unroll
                for (int nt = 0; nt < 4; nt++) {
                    const int np = nt >> 1, hh = (nt & 1) * 2;
                    mma_bf16(acc[mf][nt], aH[mf], bH[np][hh], bH[np][hh + 1]);
                    mma_bf16(acc[mf][nt], aH[mf], bL[np][hh], bL[np][hh + 1]);
                    mma_bf16(acc[mf][nt], aL[mf], bH[np][hh], bH[np][hh + 1]);
                }
        }
        __syncthreads();
    }

    // ---- fused score epilogue (deterministic: smem reduce + per-CTA partial) ----
    // acc layout: c[q]: rows g=lane>>2 (+8 for q>=2), cols (lane&3)*2 + (q&1)
    float* spart = (float*)smem;   // [4 warpN][128 rows] — stage smem is free now
    __syncthreads();               // (ensures all compute reads done before reuse)

#pragma unroll
    for (int mf = 0; mf < 4; mf++)
#pragma unroll
        for (int h = 0; h < 2; h++) {
            const int row = warpM * 64 + mf * 16 + (lane >> 2) + h * 8;
            const float* sm = (row >= rowsplit) ? sum1 : sum0;
            float s = 0.f;
#pragma unroll
            for (int nf = 0; nf < 4; nf++)
#pragma unroll
                for (int j = 0; j < 2; j++) {
                    const int col = warpN * 32 + nf * 8 + (lane & 3) * 2 + j;
                    float v = acc[mf][nf][h * 2 + j] + sm[col];
                    s += fmaxf(v, 0.f) * swf[col];
                }
            s += __shfl_xor_sync(0xffffffffu, s, 1);
            s += __shfl_xor_sync(0xffffffffu, s, 2);
            if ((lane & 3) == 0) spart[warpN * 128 + row] = s;
        }
    __syncthreads();
    if (tid < 128) {
        float s = spart[tid] + spart[128 + tid] + spart[256 + tid] + spart[384 + tid];
        part[(size_t)blockIdx.x * M_ + m0 + tid] = s;
    }
}

// ---------------------------------------------------------------------------
// Kernel D: sum partials + softmax over P (b_full shift-invariant -> dropped)
// ---------------------------------------------------------------------------
__global__ void softmax_kernel(const float* __restrict__ part,
                               float* __restrict__ alpha) {
    __shared__ float red[256];
    const int b   = blockIdx.x;
    const int tid = threadIdx.x;
    float v = -INFINITY;
    if (tid < P_) {
        const int m = b * P_ + tid;
        v = part[m] + part[M_ + m] + part[2 * M_ + m] + part[3 * M_ + m];
    }
    red[tid] = v;
    __syncthreads();
#pragma unroll
    for (int s = 128; s; s >>= 1) {
        if (tid < s) red[tid] = fmaxf(red[tid], red[tid + s]);
        __syncthreads();
    }
    const float mx = red[0];
    __syncthreads();
    float e = (tid < P_) ? expf(v - mx) : 0.f;
    red[tid] = e;
    __syncthreads();
#pragma unroll
    for (int s = 128; s; s >>= 1) {
        if (tid < s) red[tid] += red[tid + s];
        __syncthreads();
    }
    const float inv = 1.f / red[0];
    if (tid < P_) alpha[b * P_ + tid] = e * inv;
}

// ---------------------------------------------------------------------------
// Kernel E: awe[b,e] = sum_p enc[b,p,e] * alpha[b,p]   (float4)
// grid=(2, 128), block=256
// ---------------------------------------------------------------------------
__global__ void weighted_kernel(const float* __restrict__ enc,
                                const float* __restrict__ alpha,
                                float* __restrict__ out) {
    __shared__ float al[P_];
    const int b   = blockIdx.y;
    const int tid = threadIdx.x;
    if (tid < P_) al[tid] = alpha[b * P_ + tid];
    __syncthreads();

    const int e4 = blockIdx.x * 256 + tid;
    const float4* base = (const float4*)(enc + (size_t)b * P_ * E_) + e4;
    float4 acc = make_float4(0.f, 0.f, 0.f, 0.f);
#pragma unroll 4
    for (int p = 0; p < P_; p++) {
        float4 v = __ldg(base + (size_t)p * (E_ / 4));
        float a = al[p];
        acc.x = fmaf(v.x, a, acc.x);
        acc.y = fmaf(v.y, a, acc.y);
        acc.z = fmaf(v.z, a, acc.z);
        acc.w = fmaf(v.w, a, acc.w);
    }
    ((float4*)(out + (size_t)b * E_))[e4] = acc;
}

// ---------------------------------------------------------------------------
// Launch.  Inputs: encoder_out, decoder_hidden, W_enc, b_enc, W_dec, b_dec,
//                  W_full, b_full.   Output: [awe 128*2048][alpha 128*196]
// ---------------------------------------------------------------------------
extern "C" void kernel_launch(void* const* d_in, const int* in_sizes, int n_in,
                              void* d_out, int out_size) {
    const float* enc   = (const float*)d_in[0];
    const float* dh    = (const float*)d_in[1];
    const float* W_enc = (const float*)d_in[2];
    const float* b_enc = (const float*)d_in[3];
    const float* W_dec = (const float*)d_in[4];
    const float* b_dec = (const float*)d_in[5];
    const float* W_ful = (const float*)d_in[6];

    float* out   = (float*)d_out;
    float* awe   = out;
    float* alpha = out + (size_t)B_ * E_;

    __nv_bfloat16 *AHi, *ALo, *WHi, *WLo;
    float *att2, *part;
    cudaGetSymbolAddress((void**)&AHi,  g_AHi);
    cudaGetSymbolAddress((void**)&ALo,  g_ALo);
    cudaGetSymbolAddress((void**)&WHi,  g_WHi);
    cudaGetSymbolAddress((void**)&WLo,  g_WLo);
    cudaGetSymbolAddress((void**)&att2, g_att2);
    cudaGetSymbolAddress((void**)&part, g_part);

    cudaFuncSetAttribute(gemm_score_kernel,
                         cudaFuncAttributeMaxDynamicSharedMemorySize, SMEM_TOT);

    // 1. split enc and W_enc into bf16 hi/lo
    split_kernel<<<(M_ * E_ / 4 + 255) / 256, 256>>>(enc, AHi, ALo, M_ * E_ / 4);
    split_kernel<<<(E_ * A_ / 4 + 255) / 256, 256>>>(W_enc, WHi, WLo, E_ * A_ / 4);

    // 2. att2
    att2_kernel<<<B_, A_>>>(dh, W_dec, b_dec, att2);

    // 3. tensor-core GEMM + fused score partials
    gemm_score_kernel<<<dim3(4, 196), 256, SMEM_TOT>>>(
        AHi, ALo, WHi, WLo, b_enc, att2, W_ful, part);

    // 4. softmax -> alpha
    softmax_kernel<<<B_, 256>>>(part, alpha);

    // 5. weighted encoding
    weighted_kernel<<<dim3(2, B_), 256>>>(enc, alpha, awe);
}

// round 4
// speedup vs baseline: 2.7783x; 1.2662x over previous
#include <cuda_runtime.h>
#include <cuda_fp16.h>
#include <math.h>
#include <stdint.h>

#define B_   128
#define P_   196
#define E_   2048
#define A_   512
#define M_   (B_ * P_)   // 25088

// ---------------- scratch (__device__ globals; no allocs) ----------------
__device__ __align__(16) __half g_AHi[(size_t)M_ * E_];   // enc hi fp16
__device__ __align__(16) __half g_ALo[(size_t)M_ * E_];   // enc lo fp16
__device__ __align__(16) __half g_WH[(size_t)E_ * A_];    // W_enc fp16 [E,A]
__device__ float g_att2[B_ * A_];
__device__ float g_part[4 * M_];       // per-(n-block) partial scores

// ---------------- small helpers ----------------
__device__ __forceinline__ uint32_t smem_u32(const void* p) {
    uint32_t a;
    asm("{ .reg .u64 t; cvta.to.shared.u64 t, %1; cvt.u32.u64 %0, t; }"
        : "=r"(a) : "l"(p));
    return a;
}
__device__ __forceinline__ void cp16(uint32_t dst, const void* src) {
    asm volatile("cp.async.cg.shared.global [%0], [%1], 16;"
                 :: "r"(dst), "l"(src) : "memory");
}
__device__ __forceinline__ void cp_commit() {
    asm volatile("cp.async.commit_group;" ::: "memory");
}
__device__ __forceinline__ void cp_wait1() {
    asm volatile("cp.async.wait_group 1;" ::: "memory");
}
__device__ __forceinline__ void cp_wait0() {
    asm volatile("cp.async.wait_group 0;" ::: "memory");
}
__device__ __forceinline__ void ldsm_x4(uint32_t* r, uint32_t addr) {
    asm volatile("ldmatrix.sync.aligned.m8n8.x4.shared.b16 {%0,%1,%2,%3}, [%4];"
                 : "=r"(r[0]), "=r"(r[1]), "=r"(r[2]), "=r"(r[3]) : "r"(addr));
}
__device__ __forceinline__ void ldsm_x4_t(uint32_t* r, uint32_t addr) {
    asm volatile("ldmatrix.sync.aligned.m8n8.x4.trans.shared.b16 {%0,%1,%2,%3}, [%4];"
                 : "=r"(r[0]), "=r"(r[1]), "=r"(r[2]), "=r"(r[3]) : "r"(addr));
}
__device__ __forceinline__ void mma_fp16(float* c, const uint32_t* a,
                                         uint32_t b0, uint32_t b1) {
    asm volatile(
        "mma.sync.aligned.m16n8k16.row.col.f32.f16.f16.f32 "
        "{%0,%1,%2,%3}, {%4,%5,%6,%7}, {%8,%9}, {%0,%1,%2,%3};"
        : "+f"(c[0]), "+f"(c[1]), "+f"(c[2]), "+f"(c[3])
        : "r"(a[0]), "r"(a[1]), "r"(a[2]), "r"(a[3]), "r"(b0), "r"(b1));
}
__device__ __forceinline__ uint32_t pack_h2(__half x, __half y) {
    __half2 t = __halves2half2(x, y);   // x -> low 16 bits
    return *reinterpret_cast<uint32_t*>(&t);
}

// ---------------------------------------------------------------------------
// Kernel A: fp32 -> fp16 hi/lo split (elementwise, float4 granularity)
// ---------------------------------------------------------------------------
__global__ void split_kernel(const float* __restrict__ in,
                             __half* __restrict__ hi,
                             __half* __restrict__ lo, int n4) {
    int i = blockIdx.x * 256 + threadIdx.x;
    if (i >= n4) return;
    float4 v = reinterpret_cast<const float4*>(in)[i];
    __half h0 = __float2half_rn(v.x);
    __half h1 = __float2half_rn(v.y);
    __half h2 = __float2half_rn(v.z);
    __half h3 = __float2half_rn(v.w);
    __half l0 = __float2half_rn(v.x - __half2float(h0));
    __half l1 = __float2half_rn(v.y - __half2float(h1));
    __half l2 = __float2half_rn(v.z - __half2float(h2));
    __half l3 = __float2half_rn(v.w - __half2float(h3));
    reinterpret_cast<uint2*>(hi)[i] = make_uint2(pack_h2(h0, h1), pack_h2(h2, h3));
    reinterpret_cast<uint2*>(lo)[i] = make_uint2(pack_h2(l0, l1), pack_h2(l2, l3));
}

// Kernel A2: fp32 -> fp16 round (for W_enc)
__global__ void round_kernel(const float* __restrict__ in,
                             __half* __restrict__ out, int n4) {
    int i = blockIdx.x * 256 + threadIdx.x;
    if (i >= n4) return;
    float4 v = reinterpret_cast<const float4*>(in)[i];
    reinterpret_cast<uint2*>(out)[i] = make_uint2(
        pack_h2(__float2half_rn(v.x), __float2half_rn(v.y)),
        pack_h2(__float2half_rn(v.z), __float2half_rn(v.w)));
}

// ---------------------------------------------------------------------------
// Kernel B: att2 = decoder_hidden @ W_dec + b_dec   (tiny, fp32)
// ---------------------------------------------------------------------------
__global__ void att2_kernel(const float* __restrict__ dh,
                            const float* __restrict__ Wd,
                            const float* __restrict__ bd,
                            float* __restrict__ att2) {
    __shared__ float h[A_];
    const int b = blockIdx.x;
    const int a = threadIdx.x;
    h[a] = dh[b * A_ + a];
    __syncthreads();
    float acc = bd[a];
#pragma unroll 8
    for (int d = 0; d < A_; d++)
        acc += h[d] * Wd[(size_t)d * A_ + a];
    att2[b * A_ + a] = acc;
}

// ---------------------------------------------------------------------------
// Kernel C: fp16x2 (A split, W single) mma.sync GEMM with fused score epilogue.
// C_tile[128x128] = (aH + aL) @ bH ; 3-stage cp.async ring, 1 sync/chunk.
// grid=(4,196), block=256 (8 warps, 2Mx4N, warp tile 64x32)
// ---------------------------------------------------------------------------
#define BK         32
#define NKCH       (E_ / BK)        // 64
#define AS_HI      0
#define AS_LO      10240            // 128 rows * 80B
#define BS_OFF     20480            // 32 rows * 272B = 8704
#define STAGE      29184
#define NSTAGE     3
#define EPI_OFF    (NSTAGE * STAGE)            // 87552
#define SMEM_TOT   (EPI_OFF + 3 * 128 * 4)     // 89088

__global__ __launch_bounds__(256, 2)
void gemm_score_kernel(const __half* __restrict__ AHi,
                       const __half* __restrict__ ALo,
                       const __half* __restrict__ WH,
                       const float* __restrict__ bEnc,
                       const float* __restrict__ att2,
                       const float* __restrict__ Wf,
                       float* __restrict__ part) {
    extern __shared__ char smem[];
    const uint32_t sb = smem_u32(smem);
    const int tid  = threadIdx.x;
    const int lane = tid & 31;
    const int wid  = tid >> 5;
    const int warpM = wid >> 2;          // 0..1
    const int warpN = wid & 3;           // 0..3
    const int m0 = blockIdx.y * 128;
    const int n0 = blockIdx.x * 128;

    float* sum0 = (float*)(smem + EPI_OFF);
    float* sum1 = sum0 + 128;
    float* swf  = sum1 + 128;
    const int b0 = m0 / P_;
    const int rowsplit = (b0 + 1) * P_ - m0;   // rows >= this use batch b0+1
    if (tid < 128) {
        const int b1 = (b0 + 1 < B_) ? b0 + 1 : B_ - 1;
        float be = bEnc[n0 + tid];
        sum0[tid] = be + att2[b0 * A_ + n0 + tid];
        sum1[tid] = be + att2[b1 * A_ + n0 + tid];
        swf[tid]  = Wf[n0 + tid];
    }

    float acc[4][4][4];
#pragma unroll
    for (int i = 0; i < 4; i++)
#pragma unroll
        for (int j = 0; j < 4; j++)
#pragma unroll
            for (int q = 0; q < 4; q++) acc[i][j][q] = 0.f;

    // ---- stage loader (all cp.async): 1536 cp16 / stage, 6 per thread ----
    auto load_stage = [&](int st, int kc) {
        const uint32_t sbase = sb + st * STAGE;
        const int k0 = kc * BK;
#pragma unroll
        for (int i = 0; i < 2; i++) {
            int idx = tid + i * 256;               // 0..511
            int r = idx >> 2, q = idx & 3;         // A: 128 rows x 4 chunks of 16B
            size_t go = (size_t)(m0 + r) * E_ + k0 + q * 8;
            uint32_t so = (uint32_t)(r * 80 + q * 16);
            cp16(sbase + AS_HI + so, AHi + go);
            cp16(sbase + AS_LO + so, ALo + go);
        }
        {
            int idx = tid;                          // B: 32 rows x 16 chunks
            int k = idx >> 3, q = idx & 7;          // 256 threads: k 0..31, q 0..7 (2 cp each)
            size_t go = (size_t)(k0 + k) * A_ + n0 + q * 16;
            uint32_t so = (uint32_t)(k * 272 + q * 32);
            cp16(sbase + BS_OFF + so,      WH + go);
            cp16(sbase + BS_OFF + so + 16, WH + go + 8);
        }
    };

    // prologue: prefetch chunks 0 and 1
    load_stage(0, 0); cp_commit();
    load_stage(1, 1); cp_commit();
    cp_wait1();   // chunk 0 complete (chunk 1 may be in flight)

    // ldmatrix lane addressing
    const uint32_t a_row  = (uint32_t)(warpM * 64 + (lane & 15));
    const uint32_t a_colb = (uint32_t)((lane >> 4) * 16);
    const uint32_t b_krow = (uint32_t)(((lane >> 3) & 1) * 8 + (lane & 7));
    const uint32_t b_colb = (uint32_t)((warpN * 32 + (lane >> 4) * 8) * 2);

    for (int c = 0; c < NKCH; ++c) {
        __syncthreads();   // visibility of chunk c (waited at end of prev iter) + WAR guard
        if (c + 2 < NKCH) { load_stage((c + 2) % NSTAGE, c + 2); cp_commit(); }

        const uint32_t sbase = sb + (c % NSTAGE) * STAGE;
#pragma unroll
        for (int kk = 0; kk < 32; kk += 16) {
            uint32_t aH[4][4], aL[4][4], bF[2][4];
#pragma unroll
            for (int mf = 0; mf < 4; mf++) {
                uint32_t ad = sbase + (a_row + mf * 16) * 80 + kk * 2 + a_colb;
                ldsm_x4(aH[mf], ad + AS_HI);
                ldsm_x4(aL[mf], ad + AS_LO);
            }
#pragma unroll
            for (int np = 0; np < 2; np++) {
                uint32_t bd = sbase + (b_krow + kk) * 272 + b_colb + np * 32;
                ldsm_x4_t(bF[np], bd + BS_OFF);
            }
#pragma unroll
            for (int mf = 0; mf < 4; mf++)
#pragma unroll
                for (int nt = 0; nt < 4; nt++) {
                    const int np = nt >> 1, hh = (nt & 1) * 2;
                    mma_fp16(acc[mf][nt], aH[mf], bF[np][hh], bF[np][hh + 1]);
                    mma_fp16(acc[mf][nt], aL[mf], bF[np][hh], bF[np][hh + 1]);
                }
        }
        if (c + 2 < NKCH) cp_wait1(); else cp_wait0();
    }

    // ---- fused score epilogue (deterministic partials) ----
    float* spart = (float*)smem;   // stage smem free now
    __syncthreads();

#pragma unroll
    for (int mf = 0; mf < 4; mf++)
#pragma unroll
        for (int h = 0; h < 2; h++) {
            const int row = warpM * 64 + mf * 16 + (lane >> 2) + h * 8;
            const float* sm = (row >= rowsplit) ? sum1 : sum0;
            float s = 0.f;
#pragma unroll
            for (int nf = 0; nf < 4; nf++)
#pragma unroll
                for (int j = 0; j < 2; j++) {
                    const int col = warpN * 32 + nf * 8 + (lane & 3) * 2 + j;
                    float v = acc[mf][nf][h * 2 + j] + sm[col];
                    s += fmaxf(v, 0.f) * swf[col];
                }
            s += __shfl_xor_sync(0xffffffffu, s, 1);
            s += __shfl_xor_sync(0xffffffffu, s, 2);
            if ((lane & 3) == 0) spart[warpN * 128 + row] = s;
        }
    __syncthreads();
    if (tid < 128) {
        float s = spart[tid] + spart[128 + tid] + spart[256 + tid] + spart[384 + tid];
        part[(size_t)blockIdx.x * M_ + m0 + tid] = s;
    }
}

// ---------------------------------------------------------------------------
// Kernel D: sum partials + softmax over P
// ---------------------------------------------------------------------------
__global__ void softmax_kernel(const float* __restrict__ part,
                               float* __restrict__ alpha) {
    __shared__ float red[256];
    const int b   = blockIdx.x;
    const int tid = threadIdx.x;
    float v = -INFINITY;
    if (tid < P_) {
        const int m = b * P_ + tid;
        v = part[m] + part[M_ + m] + part[2 * M_ + m] + part[3 * M_ + m];
    }
    red[tid] = v;
    __syncthreads();
#pragma unroll
    for (int s = 128; s; s >>= 1) {
        if (tid < s) red[tid] = fmaxf(red[tid], red[tid + s]);
        __syncthreads();
    }
    const float mx = red[0];
    __syncthreads();
    float e = (tid < P_) ? expf(v - mx) : 0.f;
    red[tid] = e;
    __syncthreads();
#pragma unroll
    for (int s = 128; s; s >>= 1) {
        if (tid < s) red[tid] += red[tid + s];
        __syncthreads();
    }
    const float inv = 1.f / red[0];
    if (tid < P_) alpha[b * P_ + tid] = e * inv;
}

// ---------------------------------------------------------------------------
// Kernel E: awe[b,e] = sum_p enc[b,p,e] * alpha[b,p]
// grid=(4, 128), block=128 (one float4 per thread), unroll 8
// ---------------------------------------------------------------------------
__global__ void weighted_kernel(const float* __restrict__ enc,
                                const float* __restrict__ alpha,
                                float* __restrict__ out) {
    __shared__ float al[P_];
    const int b   = blockIdx.y;
    const int tid = threadIdx.x;
    for (int i = tid; i < P_; i += 128) al[i] = alpha[b * P_ + i];
    __syncthreads();

    const int e4 = blockIdx.x * 128 + tid;
    const float4* base = (const float4*)(enc + (size_t)b * P_ * E_) + e4;
    float4 acc = make_float4(0.f, 0.f, 0.f, 0.f);
#pragma unroll 8
    for (int p = 0; p < P_; p++) {
        float4 v = __ldg(base + (size_t)p * (E_ / 4));
        float a = al[p];
        acc.x = fmaf(v.x, a, acc.x);
        acc.y = fmaf(v.y, a, acc.y);
        acc.z = fmaf(v.z, a, acc.z);
        acc.w = fmaf(v.w, a, acc.w);
    }
    ((float4*)(out + (size_t)b * E_))[e4] = acc;
}

// ---------------------------------------------------------------------------
// Launch.  Inputs: encoder_out, decoder_hidden, W_enc, b_enc, W_dec, b_dec,
//                  W_full, b_full.   Output: [awe 128*2048][alpha 128*196]
// ---------------------------------------------------------------------------
extern "C" void kernel_launch(void* const* d_in, const int* in_sizes, int n_in,
                              void* d_out, int out_size) {
    const float* enc   = (const float*)d_in[0];
    const float* dh    = (const float*)d_in[1];
    const float* W_enc = (const float*)d_in[2];
    const float* b_enc = (const float*)d_in[3];
    const float* W_dec = (const float*)d_in[4];
    const float* b_dec = (const float*)d_in[5];
    const float* W_ful = (const float*)d_in[6];

    float* out   = (float*)d_out;
    float* awe   = out;
    float* alpha = out + (size_t)B_ * E_;

    __half *AHi, *ALo, *WH;
    float *att2, *part;
    cudaGetSymbolAddress((void**)&AHi,  g_AHi);
    cudaGetSymbolAddress((void**)&ALo,  g_ALo);
    cudaGetSymbolAddress((void**)&WH,   g_WH);
    cudaGetSymbolAddress((void**)&att2, g_att2);
    cudaGetSymbolAddress((void**)&part, g_part);

    cudaFuncSetAttribute(gemm_score_kernel,
                         cudaFuncAttributeMaxDynamicSharedMemorySize, SMEM_TOT);

    // 1. split enc (fp16 hi/lo) ; round W_enc (fp16)
    split_kernel<<<(M_ * E_ / 4 + 255) / 256, 256>>>(enc, AHi, ALo, M_ * E_ / 4);
    round_kernel<<<(E_ * A_ / 4 + 255) / 256, 256>>>(W_enc, WH, E_ * A_ / 4);

    // 2. att2
    att2_kernel<<<B_, A_>>>(dh, W_dec, b_dec, att2);

    // 3. tensor-core GEMM + fused score partials
    gemm_score_kernel<<<dim3(4, 196), 256, SMEM_TOT>>>(
        AHi, ALo, WH, b_enc, att2, W_ful, part);

    // 4. softmax -> alpha
    softmax_kernel<<<B_, 256>>>(part, alpha);

    // 5. weighted encoding
    weighted_kernel<<<dim3(4, B_), 128, 0>>>(enc, alpha, awe);
}

// round 5
// speedup vs baseline: 4.5045x; 1.6213x over previous
#include <cuda_runtime.h>
#include <cuda_fp16.h>
#include <math.h>
#include <stdint.h>

#define B_   128
#define P_   196
#define E_   2048
#define A_   512
#define M_   (B_ * P_)   // 25088

// ---------------- scratch (__device__ globals; no allocs) ----------------
__device__ __align__(16) __half g_AH[(size_t)M_ * E_];   // enc fp16 (rounded)
__device__ __align__(16) __half g_WH[(size_t)E_ * A_];   // W_enc fp16 [E,A]
__device__ float g_att2[B_ * A_];
__device__ float g_part[4 * M_];       // per-(n-block) partial scores

// ---------------- small helpers ----------------
__device__ __forceinline__ uint32_t smem_u32(const void* p) {
    uint32_t a;
    asm("{ .reg .u64 t; cvta.to.shared.u64 t, %1; cvt.u32.u64 %0, t; }"
        : "=r"(a) : "l"(p));
    return a;
}
__device__ __forceinline__ void cp16(uint32_t dst, const void* src) {
    asm volatile("cp.async.cg.shared.global [%0], [%1], 16;"
                 :: "r"(dst), "l"(src) : "memory");
}
__device__ __forceinline__ void cp_commit() {
    asm volatile("cp.async.commit_group;" ::: "memory");
}
__device__ __forceinline__ void cp_wait1() {
    asm volatile("cp.async.wait_group 1;" ::: "memory");
}
__device__ __forceinline__ void ldsm_x4(uint32_t* r, uint32_t addr) {
    asm volatile("ldmatrix.sync.aligned.m8n8.x4.shared.b16 {%0,%1,%2,%3}, [%4];"
                 : "=r"(r[0]), "=r"(r[1]), "=r"(r[2]), "=r"(r[3]) : "r"(addr));
}
__device__ __forceinline__ void ldsm_x4_t(uint32_t* r, uint32_t addr) {
    asm volatile("ldmatrix.sync.aligned.m8n8.x4.trans.shared.b16 {%0,%1,%2,%3}, [%4];"
                 : "=r"(r[0]), "=r"(r[1]), "=r"(r[2]), "=r"(r[3]) : "r"(addr));
}
__device__ __forceinline__ void mma_fp16(float* c, const uint32_t* a,
                                         uint32_t b0, uint32_t b1) {
    asm volatile(
        "mma.sync.aligned.m16n8k16.row.col.f32.f16.f16.f32 "
        "{%0,%1,%2,%3}, {%4,%5,%6,%7}, {%8,%9}, {%0,%1,%2,%3};"
        : "+f"(c[0]), "+f"(c[1]), "+f"(c[2]), "+f"(c[3])
        : "r"(a[0]), "r"(a[1]), "r"(a[2]), "r"(a[3]), "r"(b0), "r"(b1));
}
__device__ __forceinline__ uint32_t pack_h2(__half x, __half y) {
    __half2 t = __halves2half2(x, y);   // x -> low 16 bits
    return *reinterpret_cast<uint32_t*>(&t);
}

// ---------------------------------------------------------------------------
// Kernel A: fp32 -> fp16 round (elementwise, float4 granularity)
// ---------------------------------------------------------------------------
__global__ void round_kernel(const float* __restrict__ in,
                             __half* __restrict__ out, int n4) {
    int i = blockIdx.x * 256 + threadIdx.x;
    if (i >= n4) return;
    float4 v = reinterpret_cast<const float4*>(in)[i];
    reinterpret_cast<uint2*>(out)[i] = make_uint2(
        pack_h2(__float2half_rn(v.x), __float2half_rn(v.y)),
        pack_h2(__float2half_rn(v.z), __float2half_rn(v.w)));
}

// ---------------------------------------------------------------------------
// Kernel B: att2 = decoder_hidden @ W_dec + b_dec   (tiny, fp32)
// ---------------------------------------------------------------------------
__global__ void att2_kernel(const float* __restrict__ dh,
                            const float* __restrict__ Wd,
                            const float* __restrict__ bd,
                            float* __restrict__ att2) {
    __shared__ float h[A_];
    const int b = blockIdx.x;
    const int a = threadIdx.x;
    h[a] = dh[b * A_ + a];
    __syncthreads();
    float acc = bd[a];
#pragma unroll 8
    for (int d = 0; d < A_; d++)
        acc += h[d] * Wd[(size_t)d * A_ + a];
    att2[b * A_ + a] = acc;
}

// ---------------------------------------------------------------------------
// Kernel C: fp16 mma.sync GEMM with fused score epilogue.
// C_tile[128x128] = A[128xE] @ W[Ex128] ; BK=64, 3-stage cp.async ring.
// grid=(4,196), block=256 (8 warps, 2Mx4N, warp tile 64x32)
// ---------------------------------------------------------------------------
#define BK         64
#define NKCH       (E_ / BK)        // 32
#define A_STRIDE   144              // 128B data + 16B pad (ldsm conflict-free: 144/16=9)
#define B_STRIDE   272              // 256B data + 16B pad (272/16=17)
#define AS_SZ      (128 * A_STRIDE) // 18432
#define BS_OFF     AS_SZ
#define STAGE      (AS_SZ + 64 * B_STRIDE)     // 35840
#define NSTAGE     3
#define EPI_OFF    (NSTAGE * STAGE)            // 107520
#define SMEM_TOT   (EPI_OFF + 3 * 128 * 4)     // 109056

__global__ __launch_bounds__(256, 2)
void gemm_score_kernel(const __half* __restrict__ AH,
                       const __half* __restrict__ WH,
                       const float* __restrict__ bEnc,
                       const float* __restrict__ att2,
                       const float* __restrict__ Wf,
                       float* __restrict__ part) {
    extern __shared__ char smem[];
    const uint32_t sb = smem_u32(smem);
    const int tid  = threadIdx.x;
    const int lane = tid & 31;
    const int wid  = tid >> 5;
    const int warpM = wid >> 2;          // 0..1
    const int warpN = wid & 3;           // 0..3
    const int m0 = blockIdx.y * 128;
    const int n0 = blockIdx.x * 128;

    float* sum0 = (float*)(smem + EPI_OFF);
    float* sum1 = sum0 + 128;
    float* swf  = sum1 + 128;
    const int b0 = m0 / P_;
    const int rowsplit = (b0 + 1) * P_ - m0;   // rows >= this use batch b0+1
    if (tid < 128) {
        const int b1 = (b0 + 1 < B_) ? b0 + 1 : B_ - 1;
        float be = bEnc[n0 + tid];
        sum0[tid] = be + att2[b0 * A_ + n0 + tid];
        sum1[tid] = be + att2[b1 * A_ + n0 + tid];
        swf[tid]  = Wf[n0 + tid];
    }

    float acc[4][4][4];
#pragma unroll
    for (int i = 0; i < 4; i++)
#pragma unroll
        for (int j = 0; j < 4; j++)
#pragma unroll
            for (int q = 0; q < 4; q++) acc[i][j][q] = 0.f;

    // ---- stage loader: A 1024 cp16 + B 1024 cp16 = 8 per thread ----
    auto load_stage = [&](int st, int kc) {
        const uint32_t sbase = sb + st * STAGE;
        const int k0 = kc * BK;
#pragma unroll
        for (int i = 0; i < 4; i++) {
            int idx = tid + i * 256;               // 0..1023
            int r = idx >> 3, q = idx & 7;         // A: 128 rows x 8 chunks of 16B
            size_t go = (size_t)(m0 + r) * E_ + k0 + q * 8;
            cp16(sbase + (uint32_t)(r * A_STRIDE + q * 16), AH + go);
        }
#pragma unroll
        for (int i = 0; i < 4; i++) {
            int idx = tid + i * 256;               // 0..1023
            int k = idx >> 4, q = idx & 15;        // B: 64 rows x 16 chunks of 16B
            size_t go = (size_t)(k0 + k) * A_ + n0 + q * 8;
            cp16(sbase + BS_OFF + (uint32_t)(k * B_STRIDE + q * 16), WH + go);
        }
    };

    // prologue: prefetch chunks 0 and 1 (one commit-group each)
    load_stage(0, 0); cp_commit();
    load_stage(1, 1); cp_commit();

    // ldmatrix lane addressing
    const uint32_t a_row  = (uint32_t)(warpM * 64 + (lane & 15));
    const uint32_t a_colb = (uint32_t)((lane >> 4) * 16);
    const uint32_t b_krow = (uint32_t)(((lane >> 3) & 1) * 8 + (lane & 7));
    const uint32_t b_colb = (uint32_t)((warpN * 32 + (lane >> 4) * 8) * 2);

    for (int c = 0; c < NKCH; ++c) {
        // every iteration commits exactly one group (possibly empty), so
        // wait_group 1 here guarantees chunk c's group has completed.
        cp_wait1();
        __syncthreads();     // data visibility for all warps + WAR on reused stage
        if (c + 2 < NKCH) load_stage((c + 2) % NSTAGE, c + 2);
        cp_commit();

        const uint32_t sbase = sb + (c % NSTAGE) * STAGE;
#pragma unroll
        for (int kk = 0; kk < BK; kk += 16) {
            uint32_t aF[4][4], bF[2][4];
#pragma unroll
            for (int mf = 0; mf < 4; mf++) {
                uint32_t ad = sbase + (a_row + mf * 16) * A_STRIDE + kk * 2 + a_colb;
                ldsm_x4(aF[mf], ad);
            }
#pragma unroll
            for (int np = 0; np < 2; np++) {
                uint32_t bd = sbase + BS_OFF + (b_krow + kk) * B_STRIDE + b_colb + np * 32;
                ldsm_x4_t(bF[np], bd);
            }
#pragma unroll
            for (int mf = 0; mf < 4; mf++)
#pragma unroll
                for (int nt = 0; nt < 4; nt++) {
                    const int np = nt >> 1, hh = (nt & 1) * 2;
                    mma_fp16(acc[mf][nt], aF[mf], bF[np][hh], bF[np][hh + 1]);
                }
        }
    }

    // ---- fused score epilogue (deterministic partials) ----
    float* spart = (float*)smem;   // stage smem free now
    __syncthreads();

#pragma unroll
    for (int mf = 0; mf < 4; mf++)
#pragma unroll
        for (int h = 0; h < 2; h++) {
            const int row = warpM * 64 + mf * 16 + (lane >> 2) + h * 8;
            const float* sm = (row >= rowsplit) ? sum1 : sum0;
            float s = 0.f;
#pragma unroll
            for (int nf = 0; nf < 4; nf++)
#pragma unroll
                for (int j = 0; j < 2; j++) {
                    const int col = warpN * 32 + nf * 8 + (lane & 3) * 2 + j;
                    float v = acc[mf][nf][h * 2 + j] + sm[col];
                    s += fmaxf(v, 0.f) * swf[col];
                }
            s += __shfl_xor_sync(0xffffffffu, s, 1);
            s += __shfl_xor_sync(0xffffffffu, s, 2);
            if ((lane & 3) == 0) spart[warpN * 128 + row] = s;
        }
    __syncthreads();
    if (tid < 128) {
        float s = spart[tid] + spart[128 + tid] + spart[256 + tid] + spart[384 + tid];
        part[(size_t)blockIdx.x * M_ + m0 + tid] = s;
    }
}

// ---------------------------------------------------------------------------
// Kernel D: sum partials + softmax over P
// ---------------------------------------------------------------------------
__global__ void softmax_kernel(const float* __restrict__ part,
                               float* __restrict__ alpha) {
    __shared__ float red[256];
    const int b   = blockIdx.x;
    const int tid = threadIdx.x;
    float v = -INFINITY;
    if (tid < P_) {
        const int m = b * P_ + tid;
        v = part[m] + part[M_ + m] + part[2 * M_ + m] + part[3 * M_ + m];
    }
    red[tid] = v;
    __syncthreads();
#pragma unroll
    for (int s = 128; s; s >>= 1) {
        if (tid < s) red[tid] = fmaxf(red[tid], red[tid + s]);
        __syncthreads();
    }
    const float mx = red[0];
    __syncthreads();
    float e = (tid < P_) ? expf(v - mx) : 0.f;
    red[tid] = e;
    __syncthreads();
#pragma unroll
    for (int s = 128; s; s >>= 1) {
        if (tid < s) red[tid] += red[tid + s];
        __syncthreads();
    }
    const float inv = 1.f / red[0];
    if (tid < P_) alpha[b * P_ + tid] = e * inv;
}

// ---------------------------------------------------------------------------
// Kernel E: awe[b,e] = sum_p enc[b,p,e] * alpha[b,p]
// grid=(4, 128), block=128 (one float4 per thread), unroll 8
// ---------------------------------------------------------------------------
__global__ void weighted_kernel(const float* __restrict__ enc,
                                const float* __restrict__ alpha,
                                float* __restrict__ out) {
    __shared__ float al[P_];
    const int b   = blockIdx.y;
    const int tid = threadIdx.x;
    for (int i = tid; i < P_; i += 128) al[i] = alpha[b * P_ + i];
    __syncthreads();

    const int e4 = blockIdx.x * 128 + tid;
    const float4* base = (const float4*)(enc + (size_t)b * P_ * E_) + e4;
    float4 acc = make_float4(0.f, 0.f, 0.f, 0.f);
#pragma unroll 8
    for (int p = 0; p < P_; p++) {
        float4 v = __ldg(base + (size_t)p * (E_ / 4));
        float a = al[p];
        acc.x = fmaf(v.x, a, acc.x);
        acc.y = fmaf(v.y, a, acc.y);
        acc.z = fmaf(v.z, a, acc.z);
        acc.w = fmaf(v.w, a, acc.w);
    }
    ((float4*)(out + (size_t)b * E_))[e4] = acc;
}

// ---------------------------------------------------------------------------
// Launch.  Inputs: encoder_out, decoder_hidden, W_enc, b_enc, W_dec, b_dec,
//                  W_full, b_full.   Output: [awe 128*2048][alpha 128*196]
// ---------------------------------------------------------------------------
extern "C" void kernel_launch(void* const* d_in, const int* in_sizes, int n_in,
                              void* d_out, int out_size) {
    const float* enc   = (const float*)d_in[0];
    const float* dh    = (const float*)d_in[1];
    const float* W_enc = (const float*)d_in[2];
    const float* b_enc = (const float*)d_in[3];
    const float* W_dec = (const float*)d_in[4];
    const float* b_dec = (const float*)d_in[5];
    const float* W_ful = (const float*)d_in[6];

    float* out   = (float*)d_out;
    float* awe   = out;
    float* alpha = out + (size_t)B_ * E_;

    __half *AH, *WH;
    float *att2, *part;
    cudaGetSymbolAddress((void**)&AH,   g_AH);
    cudaGetSymbolAddress((void**)&WH,   g_WH);
    cudaGetSymbolAddress((void**)&att2, g_att2);
    cudaGetSymbolAddress((void**)&part, g_part);

    cudaFuncSetAttribute(gemm_score_kernel,
                         cudaFuncAttributeMaxDynamicSharedMemorySize, SMEM_TOT);

    // 1. round enc and W_enc to fp16
    round_kernel<<<(M_ * E_ / 4 + 255) / 256, 256>>>(enc, AH, M_ * E_ / 4);
    round_kernel<<<(E_ * A_ / 4 + 255) / 256, 256>>>(W_enc, WH, E_ * A_ / 4);

    // 2. att2
    att2_kernel<<<B_, A_>>>(dh, W_dec, b_dec, att2);

    // 3. tensor-core GEMM + fused score partials
    gemm_score_kernel<<<dim3(4, 196), 256, SMEM_TOT>>>(
        AH, WH, b_enc, att2, W_ful, part);

    // 4. softmax -> alpha
    softmax_kernel<<<B_, 256>>>(part, alpha);

    // 5. weighted encoding
    weighted_kernel<<<dim3(4, B_), 128, 0>>>(enc, alpha, awe);
}